// round 2
// baseline (speedup 1.0000x reference)
#include <cuda_runtime.h>

#define N_NODES 10000
#define D_FEAT  128
#define N_EDGES 640000

// Scratch (allocation-free per harness rules)
__device__ unsigned int g_indeg[N_NODES];
__device__ int g_is64;   // 1 if index arrays are int64, 0 if int32

// Monotone order-preserving float<->uint encoding so plain atomicMax(uint) works
__device__ __forceinline__ unsigned enc_f(float f) {
    unsigned u = __float_as_uint(f);
    return (u & 0x80000000u) ? ~u : (u | 0x80000000u);
}
__device__ __forceinline__ float dec_f(unsigned u) {
    unsigned b = (u & 0x80000000u) ? (u ^ 0x80000000u) : ~u;
    return __uint_as_float(b);
}

// enc(-inf): bits(-inf)=0xFF800000, sign set -> ~bits = 0x007FFFFF
#define ENC_NEGINF 0x007FFFFFu

__global__ void k_init(unsigned* __restrict__ out,
                       const unsigned* __restrict__ src_w,
                       const unsigned* __restrict__ dst_w) {
    int i = blockIdx.x * blockDim.x + threadIdx.x;
    if (i < N_NODES * D_FEAT) out[i] = ENC_NEGINF;
    if (i < N_NODES) g_indeg[i] = 0u;
    if (i == 0) {
        // int64 indices in [0,10000) have all-zero high (odd) words.
        unsigned o = src_w[1] | src_w[3] | src_w[5] | src_w[7]
                   | dst_w[1] | dst_w[3] | dst_w[5] | dst_w[7];
        g_is64 = (o == 0u) ? 1 : 0;
    }
}

__device__ __forceinline__ int load_idx(const void* p, int e, int is64) {
    if (is64) return (int)((const long long*)p)[e];
    return ((const int*)p)[e];
}

// One warp per edge. Each lane handles 4 consecutive features via float4.
__global__ void __launch_bounds__(256) k_edge(
    const float4* __restrict__ feats,      // [N_NODES * 32] float4
    const void* __restrict__ src,
    const void* __restrict__ dst,
    unsigned* __restrict__ out)            // [N_NODES * 128] encoded
{
    int gid  = blockIdx.x * blockDim.x + threadIdx.x;
    int e    = gid >> 5;
    int lane = gid & 31;
    if (e >= N_EDGES) return;

    int is64 = g_is64;
    int s = load_idx(src, e, is64);
    int d = load_idx(dst, e, is64);

    if (lane == 0) atomicAdd(&g_indeg[d], 1u);

    float4 v = feats[s * 32 + lane];   // 512B coalesced per warp, L2-resident
    unsigned* o = out + d * D_FEAT + lane * 4;
    atomicMax(o + 0, enc_f(v.x));
    atomicMax(o + 1, enc_f(v.y));
    atomicMax(o + 2, enc_f(v.z));
    atomicMax(o + 3, enc_f(v.w));
}

// Decode in place; DGL semantics: zero in-degree -> 0
__global__ void k_fin(float* __restrict__ out) {
    int i = blockIdx.x * blockDim.x + threadIdx.x;
    if (i >= N_NODES * D_FEAT) return;
    int n = i >> 7;  // / D_FEAT
    unsigned u = ((const unsigned*)out)[i];
    out[i] = (g_indeg[n] == 0u) ? 0.0f : dec_f(u);
}

extern "C" void kernel_launch(void* const* d_in, const int* in_sizes, int n_in,
                              void* d_out, int out_size) {
    const float* feats = (const float*)d_in[0];   // [10000,128] f32
    const void*  src   = d_in[1];                 // [640000] i32 or i64
    const void*  dst   = d_in[2];                 // [640000] i32 or i64
    float* out = (float*)d_out;

    {
        int n = N_NODES * D_FEAT;
        k_init<<<(n + 255) / 256, 256>>>((unsigned*)out,
                                         (const unsigned*)src,
                                         (const unsigned*)dst);
    }
    {
        long long total = (long long)N_EDGES * 32;
        int blocks = (int)((total + 255) / 256);
        k_edge<<<blocks, 256>>>((const float4*)feats, src, dst, (unsigned*)out);
    }
    {
        int n = N_NODES * D_FEAT;
        k_fin<<<(n + 255) / 256, 256>>>(out);
    }
}

// round 3
// speedup vs baseline: 2.8734x; 2.8734x over previous
#include <cuda_runtime.h>

#define N_NODES 10000
#define D_FEAT  128
#define N_EDGES 640000

// ---- scratch (allocation-free: __device__ globals) ----
__device__ int g_count[N_NODES];     // per-dst in-degree (rebuilt every launch)
__device__ int g_off[N_NODES + 1];   // CSR row offsets
__device__ int g_cursor[N_NODES];    // scatter cursors
__device__ int g_esrc[N_EDGES];      // src node id per CSR slot
__device__ int g_is64;               // index dtype flag

__device__ __forceinline__ int load_idx(const void* p, int e, int is64) {
    return is64 ? (int)((const long long*)p)[e] : ((const int*)p)[e];
}

// ---- 1: zero counters + detect index width ----
__global__ void k_zero(const unsigned* __restrict__ src_w,
                       const unsigned* __restrict__ dst_w) {
    int i = blockIdx.x * blockDim.x + threadIdx.x;
    if (i < N_NODES) g_count[i] = 0;
    if (i == 0) {
        // int64 indices in [0,10000) have all-zero high (odd) words.
        unsigned o = src_w[1] | src_w[3] | src_w[5] | src_w[7]
                   | dst_w[1] | dst_w[3] | dst_w[5] | dst_w[7];
        g_is64 = (o == 0u) ? 1 : 0;
    }
}

// ---- 2: histogram of dst ----
__global__ void __launch_bounds__(256) k_hist(const void* __restrict__ dst) {
    int e = blockIdx.x * blockDim.x + threadIdx.x;
    if (e >= N_EDGES) return;
    int d = load_idx(dst, e, g_is64);
    atomicAdd(&g_count[d], 1);
}

// ---- 3: exclusive scan over 10000 counts (one block, 1024 threads) ----
__global__ void __launch_bounds__(1024) k_scan() {
    const int PER = (N_NODES + 1023) / 1024;  // 10
    int tid  = threadIdx.x;
    int beg  = tid * PER;
    int end  = beg + PER; if (end > N_NODES) end = N_NODES;
    int local[PER];
    int sum = 0;
    for (int i = beg; i < end; i++) { local[i - beg] = g_count[i]; sum += local[i - beg]; }

    // inclusive scan of per-thread sums
    int lane = tid & 31, wid = tid >> 5;
    int v = sum;
    #pragma unroll
    for (int o = 1; o < 32; o <<= 1) {
        int t = __shfl_up_sync(0xffffffffu, v, o);
        if (lane >= o) v += t;
    }
    __shared__ int wsum[32];
    if (lane == 31) wsum[wid] = v;
    __syncthreads();
    if (wid == 0) {
        int w = wsum[lane];
        #pragma unroll
        for (int o = 1; o < 32; o <<= 1) {
            int t = __shfl_up_sync(0xffffffffu, w, o);
            if (lane >= o) w += t;
        }
        wsum[lane] = w;
    }
    __syncthreads();
    int excl = v - sum + (wid > 0 ? wsum[wid - 1] : 0);

    int run = excl;
    for (int i = beg; i < end; i++) {
        g_off[i] = run;
        g_cursor[i] = run;
        run += local[i - beg];
    }
    if (tid == 1023) g_off[N_NODES] = N_EDGES;
}

// ---- 4: scatter edges into CSR buckets ----
__global__ void __launch_bounds__(256) k_scatter(const void* __restrict__ src,
                                                 const void* __restrict__ dst) {
    int e = blockIdx.x * blockDim.x + threadIdx.x;
    if (e >= N_EDGES) return;
    int is64 = g_is64;
    int d = load_idx(dst, e, is64);
    int s = load_idx(src, e, is64);
    int pos = atomicAdd(&g_cursor[d], 1);
    g_esrc[pos] = s;
}

// ---- 5: gather-max, one warp per node, lane = float4 column ----
__device__ __forceinline__ float4 max4(float4 a, float4 b) {
    return make_float4(fmaxf(a.x, b.x), fmaxf(a.y, b.y),
                       fmaxf(a.z, b.z), fmaxf(a.w, b.w));
}

__global__ void __launch_bounds__(256) k_gather(const float4* __restrict__ feats,
                                                float4* __restrict__ out) {
    int gid  = blockIdx.x * blockDim.x + threadIdx.x;
    int node = gid >> 5;
    int lane = gid & 31;
    if (node >= N_NODES) return;

    int beg = g_off[node];
    int end = g_off[node + 1];

    if (beg == end) {   // DGL: zero in-degree -> 0
        out[node * 32 + lane] = make_float4(0.f, 0.f, 0.f, 0.f);
        return;
    }

    const float NI = -__int_as_float(0x7f800000);  // -inf
    float4 m0 = make_float4(NI, NI, NI, NI);
    float4 m1 = m0, m2 = m0, m3 = m0;

    int i = beg;
    for (; i + 3 < end; i += 4) {
        int s0 = g_esrc[i + 0];
        int s1 = g_esrc[i + 1];
        int s2 = g_esrc[i + 2];
        int s3 = g_esrc[i + 3];
        float4 a = feats[s0 * 32 + lane];
        float4 b = feats[s1 * 32 + lane];
        float4 c = feats[s2 * 32 + lane];
        float4 d = feats[s3 * 32 + lane];
        m0 = max4(m0, a);
        m1 = max4(m1, b);
        m2 = max4(m2, c);
        m3 = max4(m3, d);
    }
    for (; i < end; i++) {
        int s = g_esrc[i];
        m0 = max4(m0, feats[s * 32 + lane]);
    }
    m0 = max4(max4(m0, m1), max4(m2, m3));
    out[node * 32 + lane] = m0;
}

extern "C" void kernel_launch(void* const* d_in, const int* in_sizes, int n_in,
                              void* d_out, int out_size) {
    const float* feats = (const float*)d_in[0];   // [10000,128] f32
    const void*  src   = d_in[1];                 // [640000] i32 or i64
    const void*  dst   = d_in[2];                 // [640000] i32 or i64
    float4* out = (float4*)d_out;

    k_zero<<<(N_NODES + 255) / 256, 256>>>((const unsigned*)src, (const unsigned*)dst);
    k_hist<<<(N_EDGES + 255) / 256, 256>>>(dst);
    k_scan<<<1, 1024>>>();
    k_scatter<<<(N_EDGES + 255) / 256, 256>>>(src, dst);
    {
        long long total = (long long)N_NODES * 32;
        int blocks = (int)((total + 255) / 256);
        k_gather<<<blocks, 256>>>((const float4*)feats, out);
    }
}

// round 4
// speedup vs baseline: 4.0527x; 1.4104x over previous
#include <cuda_runtime.h>

#define N_NODES 10000
#define D_FEAT  128
#define N_EDGES 640000
#define CAP     256   // bucket capacity per node (mean in-degree 64, +24 sigma)

// ---- scratch (allocation-free: __device__ globals) ----
__device__ int  g_count[N_NODES];          // per-dst in-degree
__device__ int  g_esrc[N_NODES * CAP];     // bucketed src ids  (10.24 MB)
__device__ int  g_ovf_n;                   // overflow count (expected 0)
__device__ int2 g_ovf[N_EDGES];            // overflow (dst, src) pairs
__device__ int  g_is64;                    // index dtype flag

__device__ __forceinline__ int load_idx(const void* p, int e, int is64) {
    return is64 ? (int)((const long long*)p)[e] : ((const int*)p)[e];
}

// ---- 1: zero counters + detect index width ----
__global__ void k_zero(const unsigned* __restrict__ src_w,
                       const unsigned* __restrict__ dst_w) {
    int i = blockIdx.x * blockDim.x + threadIdx.x;
    if (i < N_NODES) g_count[i] = 0;
    if (i == 0) {
        // int64 indices in [0,10000) have all-zero high (odd) words.
        unsigned o = src_w[1] | src_w[3] | src_w[5] | src_w[7]
                   | dst_w[1] | dst_w[3] | dst_w[5] | dst_w[7];
        g_is64 = (o == 0u) ? 1 : 0;
        g_ovf_n = 0;
    }
}

// ---- 2: fused histogram + bucket scatter (one atomic per edge) ----
#define BUILD_E 4
__global__ void __launch_bounds__(256) k_build(const void* __restrict__ src,
                                               const void* __restrict__ dst) {
    int base = (blockIdx.x * blockDim.x + threadIdx.x) * BUILD_E;
    int is64 = g_is64;
    #pragma unroll
    for (int j = 0; j < BUILD_E; j++) {
        int e = base + j;
        if (e >= N_EDGES) return;
        int d = load_idx(dst, e, is64);
        int s = load_idx(src, e, is64);
        int r = atomicAdd(&g_count[d], 1);
        if (r < CAP) {
            g_esrc[d * CAP + r] = s;
        } else {
            int o = atomicAdd(&g_ovf_n, 1);
            g_ovf[o] = make_int2(d, s);
        }
    }
}

// ---- 3: gather-max, one warp per node, lane = float4 column ----
__device__ __forceinline__ float4 max4(float4 a, float4 b) {
    return make_float4(fmaxf(a.x, b.x), fmaxf(a.y, b.y),
                       fmaxf(a.z, b.z), fmaxf(a.w, b.w));
}

__global__ void __launch_bounds__(256) k_gather(const float4* __restrict__ feats,
                                                float4* __restrict__ out) {
    int gid  = blockIdx.x * blockDim.x + threadIdx.x;
    int node = gid >> 5;
    int lane = gid & 31;
    if (node >= N_NODES) return;

    int deg = g_count[node];

    if (deg == 0) {   // DGL: zero in-degree -> 0
        out[node * 32 + lane] = make_float4(0.f, 0.f, 0.f, 0.f);
        return;
    }

    int cnt = deg < CAP ? deg : CAP;
    const int* bucket = &g_esrc[node * CAP];

    const float NI = -__int_as_float(0x7f800000);  // -inf
    float4 m0 = make_float4(NI, NI, NI, NI);
    float4 m1 = m0, m2 = m0, m3 = m0;

    int i = 0;
    for (; i + 3 < cnt; i += 4) {
        int s0 = bucket[i + 0];
        int s1 = bucket[i + 1];
        int s2 = bucket[i + 2];
        int s3 = bucket[i + 3];
        float4 a = feats[s0 * 32 + lane];
        float4 b = feats[s1 * 32 + lane];
        float4 c = feats[s2 * 32 + lane];
        float4 d = feats[s3 * 32 + lane];
        m0 = max4(m0, a);
        m1 = max4(m1, b);
        m2 = max4(m2, c);
        m3 = max4(m3, d);
    }
    for (; i < cnt; i++) {
        m0 = max4(m0, feats[bucket[i] * 32 + lane]);
    }

    // overflow merge (expected: g_ovf_n == 0 -> one broadcast load)
    int n_ovf = g_ovf_n;
    for (int k = 0; k < n_ovf; k++) {
        int2 p = g_ovf[k];
        if (p.x == node) m0 = max4(m0, feats[p.y * 32 + lane]);
    }

    m0 = max4(max4(m0, m1), max4(m2, m3));
    out[node * 32 + lane] = m0;
}

extern "C" void kernel_launch(void* const* d_in, const int* in_sizes, int n_in,
                              void* d_out, int out_size) {
    const float* feats = (const float*)d_in[0];   // [10000,128] f32
    const void*  src   = d_in[1];                 // [640000] i32 or i64
    const void*  dst   = d_in[2];                 // [640000] i32 or i64
    float4* out = (float4*)d_out;

    k_zero<<<(N_NODES + 255) / 256, 256>>>((const unsigned*)src, (const unsigned*)dst);
    {
        int threads_needed = (N_EDGES + BUILD_E - 1) / BUILD_E;
        k_build<<<(threads_needed + 255) / 256, 256>>>(src, dst);
    }
    {
        long long total = (long long)N_NODES * 32;
        int blocks = (int)((total + 255) / 256);
        k_gather<<<blocks, 256>>>((const float4*)feats, out);
    }
}